// round 2
// baseline (speedup 1.0000x reference)
#include <cuda_runtime.h>

// CRPS loss, single-kernel version.
//   samples: [16, 4*1*256*256] fp32  (d_in[0])
//   target:  [4*1*256*256]     fp32  (d_in[1])
//   out: scalar fp32 = mean_p( sum_i|s_i-y|/16 - sum_{i<j}|s_i-s_j|/256 )
//
// term2 via sorted-order identity: sum_{i<j}|x_i-x_j| = sum_k (2k-15) x_(k)
// (ascending sort, 0-indexed rank k). 16-elem Batcher network = 63 CAS,
// each CAS = FMNMX pair on the ALU pipe -> overlaps with FMA-pipe term1.
//
// Zero-launch-overhead reduction: per-block partials + threadfence +
// atomic counter; last block reduces and resets the counter (deterministic
// across graph replays).

#define NS  16
#define P   262144
#define P4  (P / 4)
#define NT  256
#define NB  (P4 / NT)   // 256 blocks, single wave on 148 SMs

__device__ float        g_partial[NB];
__device__ unsigned int g_count = 0;

__device__ __forceinline__ void cas4(float4& a, float4& b) {
    float4 lo, hi;
    lo.x = fminf(a.x, b.x); hi.x = fmaxf(a.x, b.x);
    lo.y = fminf(a.y, b.y); hi.y = fmaxf(a.y, b.y);
    lo.z = fminf(a.z, b.z); hi.z = fmaxf(a.z, b.z);
    lo.w = fminf(a.w, b.w); hi.w = fmaxf(a.w, b.w);
    a = lo; b = hi;
}

__global__ void __launch_bounds__(NT)
k_crps(const float4* __restrict__ s, const float4* __restrict__ y,
       float* __restrict__ out) {
    const int p = blockIdx.x * NT + threadIdx.x;

    // 16 coalesced strided loads, front-batched (MLP=16)
    float4 v[NS];
#pragma unroll
    for (int i = 0; i < NS; i++) v[i] = s[i * P4 + p];
    const float4 t = y[p];

    // term1: sum_i |s_i - y|   (FMA pipe: FADD with |.| modifier)
    float a1 = 0.f;
#pragma unroll
    for (int i = 0; i < NS; i++) {
        a1 += fabsf(v[i].x - t.x) + fabsf(v[i].y - t.y)
            + fabsf(v[i].z - t.z) + fabsf(v[i].w - t.w);
    }

    // Batcher odd-even mergesort, n=16, ascending per component (63 CAS).
#pragma unroll
    for (int pp = 1; pp < NS; pp <<= 1) {
#pragma unroll
        for (int k = pp; k >= 1; k >>= 1) {
#pragma unroll
            for (int j = k % pp; j + k < NS; j += 2 * k) {
#pragma unroll
                for (int i = 0; i < k && i + j + k < NS; i++) {
                    if ((i + j) / (2 * pp) == (i + j + k) / (2 * pp))
                        cas4(v[i + j], v[i + j + k]);
                }
            }
        }
    }

    // term2 raw: sum_k (2k-15) * x_(k), coefficient shared across components
    float a2 = 0.f;
#pragma unroll
    for (int k = 0; k < NS; k++) {
        const float c = (float)(2 * k - 15);
        a2 = fmaf(c, v[k].x + v[k].y + v[k].z + v[k].w, a2);
    }

    float val = a1 * (1.0f / 16.0f) - a2 * (1.0f / 256.0f);

    // Block reduction
#pragma unroll
    for (int o = 16; o > 0; o >>= 1)
        val += __shfl_xor_sync(0xFFFFFFFFu, val, o);

    __shared__ float sm[NT / 32];
    const int lane = threadIdx.x & 31;
    const int wid  = threadIdx.x >> 5;
    if (lane == 0) sm[wid] = val;
    __syncthreads();

    if (wid == 0) {
        float w = (lane < NT / 32) ? sm[lane] : 0.f;
#pragma unroll
        for (int o = 4; o > 0; o >>= 1)
            w += __shfl_xor_sync(0xFFFFFFFFu, w, o);
        if (lane == 0) g_partial[blockIdx.x] = w;
    }

    // Last-block finalize (counter pattern; reset keeps graph replays valid)
    __shared__ bool isLast;
    if (threadIdx.x == 0) {
        __threadfence();
        unsigned int old = atomicAdd(&g_count, 1u);
        isLast = (old == NB - 1);
    }
    __syncthreads();

    if (isLast) {
        // NT == NB: one partial per thread
        double d = (double)g_partial[threadIdx.x];
#pragma unroll
        for (int o = 16; o > 0; o >>= 1)
            d += __shfl_xor_sync(0xFFFFFFFFu, d, o);

        __shared__ double sd[NT / 32];
        if (lane == 0) sd[wid] = d;
        __syncthreads();
        if (wid == 0) {
            double e = (lane < NT / 32) ? sd[lane] : 0.0;
#pragma unroll
            for (int o = 4; o > 0; o >>= 1)
                e += __shfl_xor_sync(0xFFFFFFFFu, e, o);
            if (lane == 0) {
                *out = (float)(e * (1.0 / (double)P));
                g_count = 0;
            }
        }
    }
}

extern "C" void kernel_launch(void* const* d_in, const int* in_sizes, int n_in,
                              void* d_out, int out_size) {
    const float4* samples = (const float4*)d_in[0];
    const float4* target  = (const float4*)d_in[1];
    k_crps<<<NB, NT>>>(samples, target, (float*)d_out);
}

// round 5
// speedup vs baseline: 1.1860x; 1.1860x over previous
#include <cuda_runtime.h>

// CRPS loss, one thread per pixel (scalar), single kernel.
//   samples: [16, 262144] fp32, target: [262144] fp32, out: scalar fp32.
//   crps = mean_p( sum_i|s_i-y|/16 - sum_{i<j}|s_i-s_j|/256 )
// term2 via sort identity: sum_{i<j}|x_i-x_j| = sum_k (2k-15) x_(k).
// 16-elem Batcher network = 63 CAS = 126 FMNMX (ALU pipe), overlapping
// the FMA-pipe term1 and hidden under the HBM stream.

#define NS  16
#define P   262144
#define NT  256
#define NB  (P / NT)        // 1024 blocks

__device__ float        g_partial[NB];
__device__ unsigned int g_count = 0;

__device__ __forceinline__ void cas(float& a, float& b) {
    float lo = fminf(a, b);
    float hi = fmaxf(a, b);
    a = lo; b = hi;
}

__global__ void __launch_bounds__(NT, 6)
k_crps(const float* __restrict__ s, const float* __restrict__ y,
       float* __restrict__ out) {
    const int p = blockIdx.x * NT + threadIdx.x;

    // 16 coalesced strided loads (128B per warp each), front-batched MLP=16
    float v[NS];
#pragma unroll
    for (int i = 0; i < NS; i++) v[i] = __ldg(&s[i * P + p]);
    const float t = __ldg(&y[p]);

    // term1: sum_i |s_i - y|  (FMA pipe)
    float a1 = 0.f;
#pragma unroll
    for (int i = 0; i < NS; i++) a1 += fabsf(v[i] - t);

    // Batcher odd-even mergesort, n=16 (63 compare-exchanges, ALU pipe)
#pragma unroll
    for (int pp = 1; pp < NS; pp <<= 1) {
#pragma unroll
        for (int k = pp; k >= 1; k >>= 1) {
#pragma unroll
            for (int j = k % pp; j + k < NS; j += 2 * k) {
#pragma unroll
                for (int i = 0; i < k && i + j + k < NS; i++) {
                    if ((i + j) / (2 * pp) == (i + j + k) / (2 * pp))
                        cas(v[i + j], v[i + j + k]);
                }
            }
        }
    }

    // term2 raw: sum_k (2k-15) * x_(k)
    float a2 = 0.f;
#pragma unroll
    for (int k = 0; k < NS; k++)
        a2 = fmaf((float)(2 * k - 15), v[k], a2);

    float val = a1 * (1.0f / 16.0f) - a2 * (1.0f / 256.0f);

    // Block reduction
#pragma unroll
    for (int o = 16; o > 0; o >>= 1)
        val += __shfl_xor_sync(0xFFFFFFFFu, val, o);

    __shared__ float sm[NT / 32];
    const int lane = threadIdx.x & 31;
    const int wid  = threadIdx.x >> 5;
    if (lane == 0) sm[wid] = val;
    __syncthreads();

    if (wid == 0) {
        float w = (lane < NT / 32) ? sm[lane] : 0.f;
#pragma unroll
        for (int o = 4; o > 0; o >>= 1)
            w += __shfl_xor_sync(0xFFFFFFFFu, w, o);
        if (lane == 0) g_partial[blockIdx.x] = w;
    }

    // Last-block finalize (deterministic; counter reset keeps graph replays valid)
    __shared__ bool isLast;
    if (threadIdx.x == 0) {
        __threadfence();
        isLast = (atomicAdd(&g_count, 1u) == NB - 1);
    }
    __syncthreads();

    if (isLast) {
        double d = 0.0;
#pragma unroll
        for (int r = 0; r < NB / NT; r++)
            d += (double)g_partial[threadIdx.x + r * NT];
#pragma unroll
        for (int o = 16; o > 0; o >>= 1)
            d += __shfl_xor_sync(0xFFFFFFFFu, d, o);

        __shared__ double sd[NT / 32];
        if (lane == 0) sd[wid] = d;
        __syncthreads();
        if (wid == 0) {
            double e = (lane < NT / 32) ? sd[lane] : 0.0;
#pragma unroll
            for (int o = 4; o > 0; o >>= 1)
                e += __shfl_xor_sync(0xFFFFFFFFu, e, o);
            if (lane == 0) {
                *out = (float)(e * (1.0 / (double)P));
                g_count = 0;
            }
        }
    }
}

extern "C" void kernel_launch(void* const* d_in, const int* in_sizes, int n_in,
                              void* d_out, int out_size) {
    const float* samples = (const float*)d_in[0];
    const float* target  = (const float*)d_in[1];
    k_crps<<<NB, NT>>>(samples, target, (float*)d_out);
}

// round 6
// speedup vs baseline: 1.2179x; 1.0269x over previous
#include <cuda_runtime.h>

// CRPS loss. 2 pixels per thread, all 34 loads front-batched (32 sample
// LDGs in flight per thread -> 2x bytes in flight vs 1-px version; compute
// of pixel 0 overlaps pixel 1's loads). Single wave: 512 blocks @ 4/SM.
// term2 per pixel via sort identity sum_{i<j}|xi-xj| = sum_k (2k-15)x_(k),
// 16-elem Batcher network (63 FMNMX pairs, ALU pipe).

#define NS   16
#define P    262144
#define NT   256
#define PX   2
#define NB   (P / (NT * PX))    // 512 blocks
#define STRIDE (NB * NT)        // 131072

__device__ float        g_partial[NB];
__device__ unsigned int g_count = 0;

__device__ __forceinline__ void cas(float& a, float& b) {
    float lo = fminf(a, b);
    float hi = fmaxf(a, b);
    a = lo; b = hi;
}

__device__ __forceinline__ float crps_px(float v[NS], float t) {
    // term1: sum_i |s_i - y|
    float a1 = 0.f;
#pragma unroll
    for (int i = 0; i < NS; i++) a1 += fabsf(v[i] - t);

    // Batcher odd-even mergesort, n=16 (63 CAS)
#pragma unroll
    for (int pp = 1; pp < NS; pp <<= 1) {
#pragma unroll
        for (int k = pp; k >= 1; k >>= 1) {
#pragma unroll
            for (int j = k % pp; j + k < NS; j += 2 * k) {
#pragma unroll
                for (int i = 0; i < k && i + j + k < NS; i++) {
                    if ((i + j) / (2 * pp) == (i + j + k) / (2 * pp))
                        cas(v[i + j], v[i + j + k]);
                }
            }
        }
    }

    // term2 raw: sum_k (2k-15) x_(k)
    float a2 = 0.f;
#pragma unroll
    for (int k = 0; k < NS; k++)
        a2 = fmaf((float)(2 * k - 15), v[k], a2);

    return a1 * (1.0f / 16.0f) - a2 * (1.0f / 256.0f);
}

__global__ void __launch_bounds__(NT, 4)
k_crps(const float* __restrict__ s, const float* __restrict__ y,
       float* __restrict__ out) {
    const int p0 = blockIdx.x * NT + threadIdx.x;
    const int p1 = p0 + STRIDE;

    // Front-batched loads for BOTH pixels: 32 sample LDGs + 2 target LDGs
    // independent and in flight together.
    float v0[NS], v1[NS];
#pragma unroll
    for (int i = 0; i < NS; i++) v0[i] = __ldg(&s[i * P + p0]);
#pragma unroll
    for (int i = 0; i < NS; i++) v1[i] = __ldg(&s[i * P + p1]);
    const float t0 = __ldg(&y[p0]);
    const float t1 = __ldg(&y[p1]);

    // Compute px0 while px1's loads may still be landing, then px1.
    float val = crps_px(v0, t0);
    val      += crps_px(v1, t1);

    // Block reduction
#pragma unroll
    for (int o = 16; o > 0; o >>= 1)
        val += __shfl_xor_sync(0xFFFFFFFFu, val, o);

    __shared__ float sm[NT / 32];
    const int lane = threadIdx.x & 31;
    const int wid  = threadIdx.x >> 5;
    if (lane == 0) sm[wid] = val;
    __syncthreads();

    if (wid == 0) {
        float w = (lane < NT / 32) ? sm[lane] : 0.f;
#pragma unroll
        for (int o = 4; o > 0; o >>= 1)
            w += __shfl_xor_sync(0xFFFFFFFFu, w, o);
        if (lane == 0) g_partial[blockIdx.x] = w;
    }

    // Last-block finalize (counter self-resets -> graph-replay deterministic)
    __shared__ bool isLast;
    if (threadIdx.x == 0) {
        __threadfence();
        isLast = (atomicAdd(&g_count, 1u) == NB - 1);
    }
    __syncthreads();

    if (isLast) {
        double d = 0.0;
#pragma unroll
        for (int r = 0; r < NB / NT; r++)
            d += (double)g_partial[threadIdx.x + r * NT];
#pragma unroll
        for (int o = 16; o > 0; o >>= 1)
            d += __shfl_xor_sync(0xFFFFFFFFu, d, o);

        __shared__ double sd[NT / 32];
        if (lane == 0) sd[wid] = d;
        __syncthreads();
        if (wid == 0) {
            double e = (lane < NT / 32) ? sd[lane] : 0.0;
#pragma unroll
            for (int o = 4; o > 0; o >>= 1)
                e += __shfl_xor_sync(0xFFFFFFFFu, e, o);
            if (lane == 0) {
                *out = (float)(e * (1.0 / (double)P));
                g_count = 0;
            }
        }
    }
}

extern "C" void kernel_launch(void* const* d_in, const int* in_sizes, int n_in,
                              void* d_out, int out_size) {
    const float* samples = (const float*)d_in[0];
    const float* target  = (const float*)d_in[1];
    k_crps<<<NB, NT>>>(samples, target, (float*)d_out);
}